// round 3
// baseline (speedup 1.0000x reference)
#include <cuda_runtime.h>
#include <math.h>

#define D_MODEL 1024
#define NHEAD   16
#define HDIM    64
#define BATCH   2
#define SEQ     2048
#define MTOT    (BATCH*SEQ)          // 4096
#define NQKV    (3*D_MODEL)          // 3072

typedef unsigned long long u64;

// ---- f32x2 packed helpers (SASS FFMA2) ------------------------------------
__device__ __forceinline__ u64 pk2(float x, float y) {
    u64 r; asm("mov.b64 %0, {%1, %2};" : "=l"(r) : "f"(x), "f"(y)); return r;
}
__device__ __forceinline__ u64 rep2(float x) { return pk2(x, x); }
__device__ __forceinline__ void upk2(float& x, float& y, u64 v) {
    asm("mov.b64 {%0, %1}, %2;" : "=f"(x), "=f"(y) : "l"(v));
}
#define FMA2(d, a, b) asm("fma.rn.f32x2 %0, %1, %2, %0;" : "+l"(d) : "l"(a), "l"(b))
#define SCALE2(d, s)  asm("mul.rn.f32x2 %0, %0, %1;"     : "+l"(d) : "l"(s))

// ---------------- scratch (static device globals; no allocation) ----------
// g_q, g_k stored TRANSPOSED: [B,H,Dh,T].  g_v stored [B,H,T,Dh].
__device__ float g_q[BATCH*NHEAD*HDIM*SEQ];
__device__ float g_k[BATCH*NHEAD*HDIM*SEQ];
__device__ float g_v[BATCH*NHEAD*SEQ*HDIM];
__device__ float g_attn[MTOT*D_MODEL];          // [B,T,C]

// ===========================================================================
// GEMM 1: qkv = x @ w_qkv + b_qkv -> scatter to g_q/g_k (transposed) / g_v
// 128x128x16 tile, 256 threads, 8x8 per thread, FFMA2, reg double-buffer.
// ===========================================================================
__global__ __launch_bounds__(256,2) void qkv_gemm_kernel(
    const float* __restrict__ x,
    const float* __restrict__ w,
    const float* __restrict__ bias)
{
    const int K = D_MODEL;
    const int N = NQKV;
    __shared__ float As[16][132];   // [k][m]
    __shared__ float Bs[16][128];   // [k][n]

    const int tid = threadIdx.x;
    const int tx = tid & 15;
    const int ty = tid >> 4;
    const int m0 = blockIdx.y * 128;
    const int n0 = blockIdx.x * 128;

    const int aRow = tid >> 2;      // 0..63
    const int aC4  = tid & 3;
    const int bRow = tid >> 5;      // 0..7
    const int bC4  = tid & 31;

    u64 acc2[8][4];
    #pragma unroll
    for (int i = 0; i < 8; i++)
        #pragma unroll
        for (int j = 0; j < 4; j++) acc2[i][j] = 0ull;

    float4 pa[2], pb[2];
    // prologue loads (k0 = 0)
    #pragma unroll
    for (int r = 0; r < 2; r++) {
        pa[r] = *(const float4*)(x + (m0 + aRow + r*64)*K + 0 + aC4*4);
        pb[r] = *(const float4*)(w + (0 + bRow + r*8)*N + n0 + bC4*4);
    }

    for (int k0 = 0; k0 < K; k0 += 16) {
        // store staged regs to smem
        #pragma unroll
        for (int r = 0; r < 2; r++) {
            int row = aRow + r*64;
            As[aC4*4+0][row] = pa[r].x;
            As[aC4*4+1][row] = pa[r].y;
            As[aC4*4+2][row] = pa[r].z;
            As[aC4*4+3][row] = pa[r].w;
            *(float4*)(&Bs[bRow + r*8][bC4*4]) = pb[r];
        }
        __syncthreads();

        // prefetch next k-tile (latency overlaps compute)
        if (k0 + 16 < K) {
            #pragma unroll
            for (int r = 0; r < 2; r++) {
                pa[r] = *(const float4*)(x + (m0 + aRow + r*64)*K + (k0+16) + aC4*4);
                pb[r] = *(const float4*)(w + ((k0+16) + bRow + r*8)*N + n0 + bC4*4);
            }
        }

        #pragma unroll
        for (int k = 0; k < 16; k++) {
            float a[8];
            *(float4*)(a)   = *(const float4*)(&As[k][ty*8]);
            *(float4*)(a+4) = *(const float4*)(&As[k][ty*8+4]);
            u64 b2[4];
            b2[0] = *(const u64*)(&Bs[k][tx*8 + 0]);
            b2[1] = *(const u64*)(&Bs[k][tx*8 + 2]);
            b2[2] = *(const u64*)(&Bs[k][tx*8 + 4]);
            b2[3] = *(const u64*)(&Bs[k][tx*8 + 6]);
            #pragma unroll
            for (int i = 0; i < 8; i++) {
                u64 aa = rep2(a[i]);
                FMA2(acc2[i][0], aa, b2[0]);
                FMA2(acc2[i][1], aa, b2[1]);
                FMA2(acc2[i][2], aa, b2[2]);
                FMA2(acc2[i][3], aa, b2[3]);
            }
        }
        __syncthreads();
    }

    // Epilogue: unpack, add bias, scatter. Q,K transposed [B,H,Dh,T]; V direct.
    #pragma unroll
    for (int i = 0; i < 8; i++) {
        int m = m0 + ty*8 + i;
        int bb = m / SEQ;
        int t  = m % SEQ;
        float v[8];
        upk2(v[0], v[1], acc2[i][0]);
        upk2(v[2], v[3], acc2[i][1]);
        upk2(v[4], v[5], acc2[i][2]);
        upk2(v[6], v[7], acc2[i][3]);
        #pragma unroll
        for (int j = 0; j < 8; j++) {
            int n = n0 + tx*8 + j;
            float val = v[j] + bias[n];
            int sec = n >> 10;            // 0=q,1=k,2=v
            int h   = (n & 1023) >> 6;
            int d   = n & 63;
            int bh  = bb*NHEAD + h;
            if (sec == 0)
                g_q[((size_t)bh*HDIM + d)*SEQ + t] = val;
            else if (sec == 1)
                g_k[((size_t)bh*HDIM + d)*SEQ + t] = val;
            else
                g_v[((size_t)bh*SEQ + t)*HDIM + d] = val;
        }
    }
}

// ===========================================================================
// Flash attention, 128x128 tiles, FFMA2.
// QK phase : ty=tid/16 (8 rows each), tx=tid%16 (8 cols each)  -> s2[8][4]
// PV phase : ty2=tid/8 (4 rows each), tx2=tid%8 (8 dims each)  -> o2[4][4]
// corr / 1/l handed between mappings via smem.
// ===========================================================================
#define QTILE 128
#define KTILE 128
// smem floats:
//  Qs [64][132]  = 8448    (d, t)
//  Kt [64][132]  = 8448    (d, c)
//  Vs [128][68]  = 8704    (c, d)
//  Ps [128][132] = 16896   (r, c)
//  corr[128], linv[128]
#define OFF_KT  8448
#define OFF_VS  16896
#define OFF_PS  25600
#define OFF_CR  42496
#define OFF_LI  42624
#define FLASH_SMEM_FLOATS 42752
#define FLASH_SMEM_BYTES  (FLASH_SMEM_FLOATS*4)

__global__ __launch_bounds__(256,1) void flash_attn_kernel()
{
    extern __shared__ float sm[];
    float* Qs = sm;                 // [d][t] stride 132
    float* Kt = sm + OFF_KT;        // [d][c] stride 132
    float* Vs = sm + OFF_VS;        // [c][d] stride 68
    float* Ps = sm + OFF_PS;        // [r][c] stride 132
    float* corr_s = sm + OFF_CR;    // [128]
    float* linv_s = sm + OFF_LI;    // [128]

    const int tid = threadIdx.x;
    // QK mapping
    const int tx  = tid & 15;
    const int ty  = tid >> 4;
    const int r0  = ty * 8;
    const int c0  = tx * 8;
    // PV mapping
    const int tx2 = tid & 7;
    const int ty2 = tid >> 3;
    const int pr0 = ty2 * 4;
    const int d0  = tx2 * 8;

    const int qt = blockIdx.x;
    const int h  = blockIdx.y;
    const int bb = blockIdx.z;
    const int bh = bb*NHEAD + h;

    const float* qT = g_q + (size_t)bh*HDIM*SEQ + qt*QTILE;  // + d*SEQ + t
    const float* kT = g_k + (size_t)bh*HDIM*SEQ;             // + d*SEQ + c
    const float* vb = g_v + (size_t)bh*SEQ*HDIM;             // + c*HDIM + d

    const float scale = 0.125f;   // 1/sqrt(64), folded into Q

    // load Q tile [d][t], pre-scaled (32 float4 per thread)
    for (int i4 = tid; i4 < 64*32; i4 += 256) {
        int d = i4 >> 5, t4 = i4 & 31;
        float4 v = *(const float4*)(qT + (size_t)d*SEQ + t4*4);
        v.x *= scale; v.y *= scale; v.z *= scale; v.w *= scale;
        *(float4*)(Qs + d*132 + t4*4) = v;
    }

    float m[8], l[8];
    #pragma unroll
    for (int i = 0; i < 8; i++) { m[i] = -1e30f; l[i] = 0.f; }
    u64 o2[4][4];
    #pragma unroll
    for (int i = 0; i < 4; i++)
        #pragma unroll
        for (int j = 0; j < 4; j++) o2[i][j] = 0ull;

    for (int kt = 0; kt < SEQ/KTILE; kt++) {
        __syncthreads();   // prev PV done reading Vs/Ps

        // load K^T tile [d][c]  (g_k is [Dh][T] -> coalesced)
        for (int i4 = tid; i4 < 64*32; i4 += 256) {
            int d = i4 >> 5, t4 = i4 & 31;
            *(float4*)(Kt + d*132 + t4*4) =
                *(const float4*)(kT + (size_t)d*SEQ + kt*KTILE + t4*4);
        }
        // load V tile [c][d]
        for (int i4 = tid; i4 < 128*16; i4 += 256) {
            int c = i4 >> 4, d4 = i4 & 15;
            *(float4*)(Vs + c*68 + d4*4) =
                *(const float4*)(vb + (size_t)(kt*KTILE + c)*HDIM + d4*4);
        }
        __syncthreads();

        // ---- S = (Q*scale) K^T : per-thread 8 rows x 8 cols (packed x2) ----
        u64 s2[8][4];
        #pragma unroll
        for (int i = 0; i < 8; i++)
            #pragma unroll
            for (int j = 0; j < 4; j++) s2[i][j] = 0ull;

        #pragma unroll 4
        for (int d = 0; d < 64; d++) {
            float a[8];
            *(float4*)(a)   = *(const float4*)(Qs + d*132 + r0);
            *(float4*)(a+4) = *(const float4*)(Qs + d*132 + r0 + 4);
            u64 k2[4];
            k2[0] = *(const u64*)(Kt + d*132 + c0 + 0);
            k2[1] = *(const u64*)(Kt + d*132 + c0 + 2);
            k2[2] = *(const u64*)(Kt + d*132 + c0 + 4);
            k2[3] = *(const u64*)(Kt + d*132 + c0 + 6);
            #pragma unroll
            for (int i = 0; i < 8; i++) {
                u64 aa = rep2(a[i]);
                FMA2(s2[i][0], aa, k2[0]);
                FMA2(s2[i][1], aa, k2[1]);
                FMA2(s2[i][2], aa, k2[2]);
                FMA2(s2[i][3], aa, k2[3]);
            }
        }

        // ---- online softmax (rows r0..r0+7, reduce over 16 tx lanes) ----
        #pragma unroll
        for (int i = 0; i < 8; i++) {
            float sv[8];
            upk2(sv[0], sv[1], s2[i][0]);
            upk2(sv[2], sv[3], s2[i][1]);
            upk2(sv[4], sv[5], s2[i][2]);
            upk2(sv[6], sv[7], s2[i][3]);

            float mt = fmaxf(fmaxf(fmaxf(sv[0], sv[1]), fmaxf(sv[2], sv[3])),
                             fmaxf(fmaxf(sv[4], sv[5]), fmaxf(sv[6], sv[7])));
            mt = fmaxf(mt, __shfl_xor_sync(0xffffffffu, mt, 1));
            mt = fmaxf(mt, __shfl_xor_sync(0xffffffffu, mt, 2));
            mt = fmaxf(mt, __shfl_xor_sync(0xffffffffu, mt, 4));
            mt = fmaxf(mt, __shfl_xor_sync(0xffffffffu, mt, 8));

            float mnew = fmaxf(m[i], mt);
            float cr = __expf(m[i] - mnew);
            m[i] = mnew;

            float rs = 0.f;
            #pragma unroll
            for (int j = 0; j < 8; j++) { sv[j] = __expf(sv[j] - mnew); rs += sv[j]; }
            rs += __shfl_xor_sync(0xffffffffu, rs, 1);
            rs += __shfl_xor_sync(0xffffffffu, rs, 2);
            rs += __shfl_xor_sync(0xffffffffu, rs, 4);
            rs += __shfl_xor_sync(0xffffffffu, rs, 8);
            l[i] = l[i]*cr + rs;

            if (tx == 0) corr_s[r0 + i] = cr;

            *(float4*)(Ps + (r0+i)*132 + c0)     = make_float4(sv[0], sv[1], sv[2], sv[3]);
            *(float4*)(Ps + (r0+i)*132 + c0 + 4) = make_float4(sv[4], sv[5], sv[6], sv[7]);
        }
        __syncthreads();   // Ps + corr visible to all (PV uses different mapping)

        // ---- PV: rows pr0..pr0+3, dims d0..d0+7 (packed x2) ----
        {
            // rescale existing accumulator by this tile's corr
            #pragma unroll
            for (int i = 0; i < 4; i++) {
                u64 cc = rep2(corr_s[pr0 + i]);
                SCALE2(o2[i][0], cc);
                SCALE2(o2[i][1], cc);
                SCALE2(o2[i][2], cc);
                SCALE2(o2[i][3], cc);
            }

            for (int c4 = 0; c4 < KTILE/4; c4++) {
                float p[4][4];
                #pragma unroll
                for (int i = 0; i < 4; i++)
                    *(float4*)(p[i]) = *(const float4*)(Ps + (pr0+i)*132 + c4*4);
                #pragma unroll
                for (int cc = 0; cc < 4; cc++) {
                    int c = c4*4 + cc;
                    u64 v2[4];
                    v2[0] = *(const u64*)(Vs + c*68 + d0 + 0);
                    v2[1] = *(const u64*)(Vs + c*68 + d0 + 2);
                    v2[2] = *(const u64*)(Vs + c*68 + d0 + 4);
                    v2[3] = *(const u64*)(Vs + c*68 + d0 + 6);
                    #pragma unroll
                    for (int i = 0; i < 4; i++) {
                        u64 pp = rep2(p[i][cc]);
                        FMA2(o2[i][0], pp, v2[0]);
                        FMA2(o2[i][1], pp, v2[1]);
                        FMA2(o2[i][2], pp, v2[2]);
                        FMA2(o2[i][3], pp, v2[3]);
                    }
                }
            }
        }
    }

    // hand 1/l to PV mapping
    if (tx == 0) {
        #pragma unroll
        for (int i = 0; i < 8; i++) linv_s[r0 + i] = 1.0f / l[i];
    }
    __syncthreads();

    // epilogue: normalize, write [B,T,C] with C=(h,d)
    #pragma unroll
    for (int i = 0; i < 4; i++) {
        float inv = linv_s[pr0 + i];
        float v[8];
        upk2(v[0], v[1], o2[i][0]);
        upk2(v[2], v[3], o2[i][1]);
        upk2(v[4], v[5], o2[i][2]);
        upk2(v[6], v[7], o2[i][3]);
        float* dst = g_attn + (size_t)(bb*SEQ + qt*QTILE + pr0 + i)*D_MODEL + h*64 + d0;
        *(float4*)(dst)     = make_float4(v[0]*inv, v[1]*inv, v[2]*inv, v[3]*inv);
        *(float4*)(dst + 4) = make_float4(v[4]*inv, v[5]*inv, v[6]*inv, v[7]*inv);
    }
}

// ===========================================================================
// GEMM 3: out = attn @ w_out + b_out   [4096,1024] @ [1024,1024]
// ===========================================================================
__global__ __launch_bounds__(256,2) void out_gemm_kernel(
    const float* __restrict__ w,
    const float* __restrict__ bias,
    float* __restrict__ out)
{
    const int K = D_MODEL;
    const int N = D_MODEL;
    const float* __restrict__ A = g_attn;

    __shared__ float As[16][132];
    __shared__ float Bs[16][128];

    const int tid = threadIdx.x;
    const int tx = tid & 15;
    const int ty = tid >> 4;
    const int m0 = blockIdx.y * 128;
    const int n0 = blockIdx.x * 128;

    const int aRow = tid >> 2;
    const int aC4  = tid & 3;
    const int bRow = tid >> 5;
    const int bC4  = tid & 31;

    u64 acc2[8][4];
    #pragma unroll
    for (int i = 0; i < 8; i++)
        #pragma unroll
        for (int j = 0; j < 4; j++) acc2[i][j] = 0ull;

    float4 pa[2], pb[2];
    #pragma unroll
    for (int r = 0; r < 2; r++) {
        pa[r] = *(const float4*)(A + (m0 + aRow + r*64)*K + 0 + aC4*4);
        pb[r] = *(const float4*)(w + (0 + bRow + r*8)*N + n0 + bC4*4);
    }

    for (int k0 = 0; k0 < K; k0 += 16) {
        #pragma unroll
        for (int r = 0; r < 2; r++) {
            int row = aRow + r*64;
            As[aC4*4+0][row] = pa[r].x;
            As[aC4*4+1][row] = pa[r].y;
            As[aC4*4+2][row] = pa[r].z;
            As[aC4*4+3][row] = pa[r].w;
            *(float4*)(&Bs[bRow + r*8][bC4*4]) = pb[r];
        }
        __syncthreads();

        if (k0 + 16 < K) {
            #pragma unroll
            for (int r = 0; r < 2; r++) {
                pa[r] = *(const float4*)(A + (m0 + aRow + r*64)*K + (k0+16) + aC4*4);
                pb[r] = *(const float4*)(w + ((k0+16) + bRow + r*8)*N + n0 + bC4*4);
            }
        }

        #pragma unroll
        for (int k = 0; k < 16; k++) {
            float a[8];
            *(float4*)(a)   = *(const float4*)(&As[k][ty*8]);
            *(float4*)(a+4) = *(const float4*)(&As[k][ty*8+4]);
            u64 b2[4];
            b2[0] = *(const u64*)(&Bs[k][tx*8 + 0]);
            b2[1] = *(const u64*)(&Bs[k][tx*8 + 2]);
            b2[2] = *(const u64*)(&Bs[k][tx*8 + 4]);
            b2[3] = *(const u64*)(&Bs[k][tx*8 + 6]);
            #pragma unroll
            for (int i = 0; i < 8; i++) {
                u64 aa = rep2(a[i]);
                FMA2(acc2[i][0], aa, b2[0]);
                FMA2(acc2[i][1], aa, b2[1]);
                FMA2(acc2[i][2], aa, b2[2]);
                FMA2(acc2[i][3], aa, b2[3]);
            }
        }
        __syncthreads();
    }

    #pragma unroll
    for (int i = 0; i < 8; i++) {
        int mrow = m0 + ty*8 + i;
        float v[8];
        upk2(v[0], v[1], acc2[i][0]);
        upk2(v[2], v[3], acc2[i][1]);
        upk2(v[4], v[5], acc2[i][2]);
        upk2(v[6], v[7], acc2[i][3]);
        #pragma unroll
        for (int j = 0; j < 8; j += 4) {
            int n = n0 + tx*8 + j;
            float4 o;
            o.x = v[j+0] + bias[n+0];
            o.y = v[j+1] + bias[n+1];
            o.z = v[j+2] + bias[n+2];
            o.w = v[j+3] + bias[n+3];
            *(float4*)(out + mrow*N + n) = o;
        }
    }
}

// ===========================================================================
extern "C" void kernel_launch(void* const* d_in, const int* in_sizes, int n_in,
                              void* d_out, int out_size)
{
    const float* x     = (const float*)d_in[0];
    const float* w_qkv = (const float*)d_in[1];
    const float* b_qkv = (const float*)d_in[2];
    const float* w_out = (const float*)d_in[3];
    const float* b_out = (const float*)d_in[4];
    float* out = (float*)d_out;

    (void)in_sizes; (void)n_in; (void)out_size;

    cudaFuncSetAttribute(flash_attn_kernel,
                         cudaFuncAttributeMaxDynamicSharedMemorySize,
                         FLASH_SMEM_BYTES);

    // 1) QKV GEMM + bias + scatter (Q,K transposed)
    {
        dim3 grid(NQKV/128, MTOT/128);   // (24, 32)
        qkv_gemm_kernel<<<grid, 256>>>(x, w_qkv, b_qkv);
    }
    // 2) flash attention
    {
        dim3 grid(SEQ/QTILE, NHEAD, BATCH); // (16, 16, 2)
        flash_attn_kernel<<<grid, 256, FLASH_SMEM_BYTES>>>();
    }
    // 3) output GEMM + bias
    {
        dim3 grid(D_MODEL/128, MTOT/128); // (8, 32)
        out_gemm_kernel<<<grid, 256>>>(w_out, b_out, out);
    }
}

// round 5
// speedup vs baseline: 2.3798x; 2.3798x over previous
#include <cuda_runtime.h>
#include <cstdint>

#define D_MODEL 1024
#define NHEAD   16
#define HDIM    64
#define BATCH   2
#define SEQ     2048
#define MTOT    (BATCH*SEQ)          // 4096
#define NQKV    (3*D_MODEL)          // 3072

// ---------------- scratch (static device globals; no allocation) ----------
__device__ float g_q[BATCH*NHEAD*HDIM*SEQ];     // [B,H,Dh,T]
__device__ float g_k[BATCH*NHEAD*HDIM*SEQ];     // [B,H,Dh,T]
__device__ float g_v[BATCH*NHEAD*SEQ*HDIM];     // [B,H,T,Dh]
__device__ float g_attn[MTOT*D_MODEL];          // [B,T,C]

// ---------------- tf32 mma helpers ----------------------------------------
__device__ __forceinline__ uint32_t f2tf(float x) {
    uint32_t r; asm("cvt.rna.tf32.f32 %0, %1;" : "=r"(r) : "f"(x)); return r;
}
__device__ __forceinline__ uint4 cvt4(float4 v) {
    return make_uint4(f2tf(v.x), f2tf(v.y), f2tf(v.z), f2tf(v.w));
}
__device__ __forceinline__ uint4 cvt4s(float4 v, float s) {
    return make_uint4(f2tf(v.x*s), f2tf(v.y*s), f2tf(v.z*s), f2tf(v.w*s));
}
__device__ __forceinline__ void mma8(float* c,
    uint32_t a0, uint32_t a1, uint32_t a2, uint32_t a3,
    uint32_t b0, uint32_t b1)
{
    asm volatile(
        "mma.sync.aligned.m16n8k8.row.col.f32.tf32.tf32.f32 "
        "{%0,%1,%2,%3}, {%4,%5,%6,%7}, {%8,%9}, {%0,%1,%2,%3};"
        : "+f"(c[0]), "+f"(c[1]), "+f"(c[2]), "+f"(c[3])
        : "r"(a0), "r"(a1), "r"(a2), "r"(a3), "r"(b0), "r"(b1));
}

// ===========================================================================
// tf32 MMA GEMM: C[128,128] tile = A[m0:,1024] @ W[:, n0:]  (both row-major)
// 8 warps: wm = wid&3 (32 rows), wn = wid>>2 (64 cols). K chunk = 16.
// sA [128][20] (row, k) ; sB [16][132] (k, n). Double buffered.
// ===========================================================================
#define SA_STRIDE 20
#define SB_STRIDE 132

__device__ __forceinline__ void gemm_tile_tf32(
    const float* __restrict__ A, const float* __restrict__ W, int ldW,
    int m0, int n0,
    uint32_t (*sA)[128*SA_STRIDE], uint32_t (*sB)[16*SB_STRIDE],
    float acc[2][8][4])
{
    const int tid  = threadIdx.x;
    const int lane = tid & 31;
    const int wid  = tid >> 5;
    const int wm   = wid & 3;
    const int wn   = wid >> 2;
    const int lq   = lane & 3;     // k-in-group / col-pair
    const int gq   = lane >> 2;    // row-in-group

    const int arow = tid >> 1;            // 0..127
    const int ac8  = (tid & 1) * 8;       // 0 or 8
    const int brow = tid >> 4;            // 0..15
    const int bc   = (tid & 15) * 4;      // 0..60

    const float* Abase = A + (size_t)(m0 + arow)*D_MODEL + ac8;
    const float* Wbase = W + (size_t)brow*ldW + n0 + bc;

    float4 pa0, pa1, pb0, pb1;
    pa0 = *(const float4*)(Abase + 0);
    pa1 = *(const float4*)(Abase + 4);
    pb0 = *(const float4*)(Wbase + 0);
    pb1 = *(const float4*)(Wbase + 64);

    *(uint4*)&sA[0][arow*SA_STRIDE + ac8 + 0] = cvt4(pa0);
    *(uint4*)&sA[0][arow*SA_STRIDE + ac8 + 4] = cvt4(pa1);
    *(uint4*)&sB[0][brow*SB_STRIDE + bc]      = cvt4(pb0);
    *(uint4*)&sB[0][brow*SB_STRIDE + bc + 64] = cvt4(pb1);
    __syncthreads();

    for (int c = 0; c < 64; c++) {
        const int buf = c & 1;
        if (c < 63) {
            int k0 = (c + 1) * 16;
            pa0 = *(const float4*)(Abase + k0 + 0);
            pa1 = *(const float4*)(Abase + k0 + 4);
            pb0 = *(const float4*)(Wbase + (size_t)k0*ldW + 0);
            pb1 = *(const float4*)(Wbase + (size_t)k0*ldW + 64);
        }

        #pragma unroll
        for (int kk = 0; kk < 2; kk++) {
            const int kb = kk*8 + lq;
            uint32_t a[2][4];
            #pragma unroll
            for (int mt = 0; mt < 2; mt++) {
                int r = wm*32 + mt*16 + gq;
                a[mt][0] = sA[buf][ r      *SA_STRIDE + kb    ];
                a[mt][1] = sA[buf][(r + 8) *SA_STRIDE + kb    ];
                a[mt][2] = sA[buf][ r      *SA_STRIDE + kb + 4];
                a[mt][3] = sA[buf][(r + 8) *SA_STRIDE + kb + 4];
            }
            #pragma unroll
            for (int nt = 0; nt < 8; nt++) {
                int nb = wn*64 + nt*8 + gq;
                uint32_t b0 = sB[buf][ kb      *SB_STRIDE + nb];
                uint32_t b1 = sB[buf][(kb + 4) *SB_STRIDE + nb];
                mma8(acc[0][nt], a[0][0], a[0][1], a[0][2], a[0][3], b0, b1);
                mma8(acc[1][nt], a[1][0], a[1][1], a[1][2], a[1][3], b0, b1);
            }
        }

        if (c < 63) {
            int nb = buf ^ 1;
            *(uint4*)&sA[nb][arow*SA_STRIDE + ac8 + 0] = cvt4(pa0);
            *(uint4*)&sA[nb][arow*SA_STRIDE + ac8 + 4] = cvt4(pa1);
            *(uint4*)&sB[nb][brow*SB_STRIDE + bc]      = cvt4(pb0);
            *(uint4*)&sB[nb][brow*SB_STRIDE + bc + 64] = cvt4(pb1);
        }
        __syncthreads();
    }
}

// ---- GEMM 1: qkv = x @ w_qkv + b, scatter q/k transposed, v direct --------
__global__ __launch_bounds__(256,2) void qkv_mma_kernel(
    const float* __restrict__ x,
    const float* __restrict__ w,
    const float* __restrict__ bias)
{
    __shared__ uint32_t sA[2][128*SA_STRIDE];
    __shared__ uint32_t sB[2][16*SB_STRIDE];

    const int n0 = blockIdx.x * 128;
    const int m0 = blockIdx.y * 128;
    const int lane = threadIdx.x & 31;
    const int wid  = threadIdx.x >> 5;
    const int wm = wid & 3, wn = wid >> 2;
    const int lq = lane & 3, gq = lane >> 2;

    float acc[2][8][4];
    #pragma unroll
    for (int i = 0; i < 2; i++)
        #pragma unroll
        for (int j = 0; j < 8; j++)
            #pragma unroll
            for (int k = 0; k < 4; k++) acc[i][j][k] = 0.f;

    gemm_tile_tf32(x, w, NQKV, m0, n0, sA, sB, acc);

    #pragma unroll
    for (int mt = 0; mt < 2; mt++) {
        int rbase = m0 + wm*32 + mt*16 + gq;
        #pragma unroll
        for (int half = 0; half < 2; half++) {
            int row = rbase + half*8;
            int bb = row >> 11;          // /SEQ
            int t  = row & 2047;
            #pragma unroll
            for (int nt = 0; nt < 8; nt++) {
                int n = n0 + wn*64 + nt*8 + lq*2;
                float v0 = acc[mt][nt][half*2+0] + __ldg(bias + n);
                float v1 = acc[mt][nt][half*2+1] + __ldg(bias + n + 1);
                int sec = n >> 10;
                int h   = (n >> 6) & 15;
                int d   = n & 63;
                int bh  = bb*NHEAD + h;
                if (sec == 2) {
                    *(float2*)&g_v[((size_t)bh*SEQ + t)*HDIM + d] = make_float2(v0, v1);
                } else {
                    float* p = sec ? g_k : g_q;
                    p[((size_t)bh*HDIM + d    )*SEQ + t] = v0;
                    p[((size_t)bh*HDIM + d + 1)*SEQ + t] = v1;
                }
            }
        }
    }
}

// ---- GEMM 3: out = attn @ w_out + b ----------------------------------------
__global__ __launch_bounds__(256,2) void out_mma_kernel(
    const float* __restrict__ w,
    const float* __restrict__ bias,
    float* __restrict__ out)
{
    __shared__ uint32_t sA[2][128*SA_STRIDE];
    __shared__ uint32_t sB[2][16*SB_STRIDE];

    const int n0 = blockIdx.x * 128;
    const int m0 = blockIdx.y * 128;
    const int lane = threadIdx.x & 31;
    const int wid  = threadIdx.x >> 5;
    const int wm = wid & 3, wn = wid >> 2;
    const int lq = lane & 3, gq = lane >> 2;

    float acc[2][8][4];
    #pragma unroll
    for (int i = 0; i < 2; i++)
        #pragma unroll
        for (int j = 0; j < 8; j++)
            #pragma unroll
            for (int k = 0; k < 4; k++) acc[i][j][k] = 0.f;

    gemm_tile_tf32(g_attn, w, D_MODEL, m0, n0, sA, sB, acc);

    #pragma unroll
    for (int mt = 0; mt < 2; mt++) {
        int rbase = m0 + wm*32 + mt*16 + gq;
        #pragma unroll
        for (int half = 0; half < 2; half++) {
            int row = rbase + half*8;
            #pragma unroll
            for (int nt = 0; nt < 8; nt++) {
                int n = n0 + wn*64 + nt*8 + lq*2;
                float v0 = acc[mt][nt][half*2+0] + __ldg(bias + n);
                float v1 = acc[mt][nt][half*2+1] + __ldg(bias + n + 1);
                *(float2*)&out[(size_t)row*D_MODEL + n] = make_float2(v0, v1);
            }
        }
    }
}

// ===========================================================================
// Flash attention with tf32 MMA. QTILE=128 rows/CTA, KTILE=64.
// 8 warps x 16 rows: warp owns rows r0..r0+15 entirely (m16 tile).
// smem (uint32 words):
//   Qs [64][132]  off 0      (d, t)   8448
//   Kt [64][68]   off 8448   (d, c)   4352
//   Vs [64][68]   off 12800  (c, d)   4352
//   Ps [128][68]  off 17152  (r, c)   8704
#define QTILE 128
#define KTILE 64
#define FL_OFF_KT 8448
#define FL_OFF_VS 12800
#define FL_OFF_PS 17152
#define FLASH_SMEM_WORDS 25856
#define FLASH_SMEM_BYTES (FLASH_SMEM_WORDS*4)

__global__ __launch_bounds__(256,2) void flash_mma_kernel()
{
    extern __shared__ uint32_t smu[];
    uint32_t* Qs = smu;                 // [d][t] stride 132
    uint32_t* Kt = smu + FL_OFF_KT;     // [d][c] stride 68
    uint32_t* Vs = smu + FL_OFF_VS;     // [c][d] stride 68
    uint32_t* Ps = smu + FL_OFF_PS;     // [r][c] stride 68

    const int tid  = threadIdx.x;
    const int lane = tid & 31;
    const int wid  = tid >> 5;
    const int lq   = lane & 3;
    const int gq   = lane >> 2;
    const int r0   = wid * 16;

    const int qt = blockIdx.x;
    const int h  = blockIdx.y;
    const int bb = blockIdx.z;
    const int bh = bb*NHEAD + h;

    const float* qT = g_q + (size_t)bh*HDIM*SEQ + qt*QTILE;  // + d*SEQ + t
    const float* kT = g_k + (size_t)bh*HDIM*SEQ;             // + d*SEQ + c
    const float* vb = g_v + (size_t)bh*SEQ*HDIM;             // + c*HDIM + d

    const float scale = 0.125f;

    // load Q tile [d][t] as tf32, pre-scaled
    for (int i = tid; i < 64*32; i += 256) {
        int d = i >> 5, t4 = i & 31;
        float4 v = *(const float4*)(qT + (size_t)d*SEQ + t4*4);
        *(uint4*)&Qs[d*132 + t4*4] = cvt4s(v, scale);
    }

    float m0 = -1e30f, m1 = -1e30f, l0 = 0.f, l1 = 0.f;
    float o[8][4];
    #pragma unroll
    for (int i = 0; i < 8; i++)
        #pragma unroll
        for (int j = 0; j < 4; j++) o[i][j] = 0.f;

    const int row0 = r0 + gq;
    const int row1 = row0 + 8;

    for (int kt = 0; kt < SEQ/KTILE; kt++) {
        __syncthreads();   // prev iter done reading Kt/Vs

        for (int i = tid; i < 64*16; i += 256) {
            int d = i >> 4, c4 = i & 15;
            float4 v = *(const float4*)(kT + (size_t)d*SEQ + kt*KTILE + c4*4);
            *(uint4*)&Kt[d*68 + c4*4] = cvt4(v);
        }
        for (int i = tid; i < 64*16; i += 256) {
            int c = i >> 4, d4 = i & 15;
            float4 v = *(const float4*)(vb + (size_t)(kt*KTILE + c)*HDIM + d4*4);
            *(uint4*)&Vs[c*68 + d4*4] = cvt4(v);
        }
        __syncthreads();

        // ---- S = Q K^T : warp tile 16 x 64, 8 k-steps over d ----
        float s[8][4];
        #pragma unroll
        for (int nt = 0; nt < 8; nt++)
            #pragma unroll
            for (int j = 0; j < 4; j++) s[nt][j] = 0.f;

        #pragma unroll
        for (int kk = 0; kk < 8; kk++) {
            int kb = kk*8 + lq;
            uint32_t a0 = Qs[ kb     *132 + row0];
            uint32_t a1 = Qs[ kb     *132 + row1];
            uint32_t a2 = Qs[(kb + 4)*132 + row0];
            uint32_t a3 = Qs[(kb + 4)*132 + row1];
            #pragma unroll
            for (int nt = 0; nt < 8; nt++) {
                uint32_t b0 = Kt[ kb     *68 + nt*8 + gq];
                uint32_t b1 = Kt[(kb + 4)*68 + nt*8 + gq];
                mma8(s[nt], a0, a1, a2, a3, b0, b1);
            }
        }

        // ---- online softmax: rows row0 (s[nt][0,1]) and row1 (s[nt][2,3]) ----
        float mt0 = -1e30f, mt1 = -1e30f;
        #pragma unroll
        for (int nt = 0; nt < 8; nt++) {
            mt0 = fmaxf(mt0, fmaxf(s[nt][0], s[nt][1]));
            mt1 = fmaxf(mt1, fmaxf(s[nt][2], s[nt][3]));
        }
        mt0 = fmaxf(mt0, __shfl_xor_sync(0xffffffffu, mt0, 1));
        mt0 = fmaxf(mt0, __shfl_xor_sync(0xffffffffu, mt0, 2));
        mt1 = fmaxf(mt1, __shfl_xor_sync(0xffffffffu, mt1, 1));
        mt1 = fmaxf(mt1, __shfl_xor_sync(0xffffffffu, mt1, 2));

        float mn0 = fmaxf(m0, mt0);
        float mn1 = fmaxf(m1, mt1);
        float corr0 = __expf(m0 - mn0);
        float corr1 = __expf(m1 - mn1);
        m0 = mn0; m1 = mn1;

        float sum0 = 0.f, sum1 = 0.f;
        #pragma unroll
        for (int nt = 0; nt < 8; nt++) {
            float p0 = __expf(s[nt][0] - mn0);
            float p1 = __expf(s[nt][1] - mn0);
            float p2 = __expf(s[nt][2] - mn1);
            float p3 = __expf(s[nt][3] - mn1);
            sum0 += p0 + p1;
            sum1 += p2 + p3;
            *(uint2*)&Ps[row0*68 + nt*8 + lq*2] = make_uint2(f2tf(p0), f2tf(p1));
            *(uint2*)&Ps[row1*68 + nt*8 + lq*2] = make_uint2(f2tf(p2), f2tf(p3));
        }
        sum0 += __shfl_xor_sync(0xffffffffu, sum0, 1);
        sum0 += __shfl_xor_sync(0xffffffffu, sum0, 2);
        sum1 += __shfl_xor_sync(0xffffffffu, sum1, 1);
        sum1 += __shfl_xor_sync(0xffffffffu, sum1, 2);
        l0 = l0*corr0 + sum0;
        l1 = l1*corr1 + sum1;

        #pragma unroll
        for (int nt = 0; nt < 8; nt++) {
            o[nt][0] *= corr0; o[nt][1] *= corr0;
            o[nt][2] *= corr1; o[nt][3] *= corr1;
        }
        __syncwarp();   // Ps rows warp-private; make writes visible within warp

        // ---- O += P V : warp tile 16 x 64, 8 k-steps over c ----
        #pragma unroll
        for (int kk = 0; kk < 8; kk++) {
            int kb = kk*8 + lq;
            uint32_t a0 = Ps[row0*68 + kb    ];
            uint32_t a1 = Ps[row1*68 + kb    ];
            uint32_t a2 = Ps[row0*68 + kb + 4];
            uint32_t a3 = Ps[row1*68 + kb + 4];
            #pragma unroll
            for (int nt = 0; nt < 8; nt++) {
                uint32_t b0 = Vs[ kb     *68 + nt*8 + gq];
                uint32_t b1 = Vs[(kb + 4)*68 + nt*8 + gq];
                mma8(o[nt], a0, a1, a2, a3, b0, b1);
            }
        }
        __syncwarp();   // done reading Ps before next iter overwrites
    }

    // epilogue: normalize, write [B,T,C] with C=(h,d)
    float inv0 = 1.0f / l0;
    float inv1 = 1.0f / l1;
    #pragma unroll
    for (int nt = 0; nt < 8; nt++) {
        int d = nt*8 + lq*2;
        float* dst0 = g_attn + (size_t)(bb*SEQ + qt*QTILE + row0)*D_MODEL + h*64 + d;
        float* dst1 = g_attn + (size_t)(bb*SEQ + qt*QTILE + row1)*D_MODEL + h*64 + d;
        *(float2*)dst0 = make_float2(o[nt][0]*inv0, o[nt][1]*inv0);
        *(float2*)dst1 = make_float2(o[nt][2]*inv1, o[nt][3]*inv1);
    }
}

// ===========================================================================
extern "C" void kernel_launch(void* const* d_in, const int* in_sizes, int n_in,
                              void* d_out, int out_size)
{
    const float* x     = (const float*)d_in[0];
    const float* w_qkv = (const float*)d_in[1];
    const float* b_qkv = (const float*)d_in[2];
    const float* w_out = (const float*)d_in[3];
    const float* b_out = (const float*)d_in[4];
    float* out = (float*)d_out;

    (void)in_sizes; (void)n_in; (void)out_size;

    cudaFuncSetAttribute(flash_mma_kernel,
                         cudaFuncAttributeMaxDynamicSharedMemorySize,
                         FLASH_SMEM_BYTES);

    // 1) QKV GEMM (tf32 MMA) + bias + scatter
    {
        dim3 grid(NQKV/128, MTOT/128);    // (24, 32)
        qkv_mma_kernel<<<grid, 256>>>(x, w_qkv, b_qkv);
    }
    // 2) flash attention (tf32 MMA)
    {
        dim3 grid(SEQ/QTILE, NHEAD, BATCH); // (16, 16, 2)
        flash_mma_kernel<<<grid, 256, FLASH_SMEM_BYTES>>>();
    }
    // 3) out GEMM (tf32 MMA) + bias
    {
        dim3 grid(D_MODEL/128, MTOT/128); // (8, 32)
        out_mma_kernel<<<grid, 256>>>(w_out, b_out, out);
    }
}

// round 6
// speedup vs baseline: 2.4681x; 1.0371x over previous
#include <cuda_runtime.h>
#include <cstdint>

#define D_MODEL 1024
#define NHEAD   16
#define HDIM    64
#define BATCH   2
#define SEQ     2048
#define MTOT    (BATCH*SEQ)          // 4096
#define NQKV    (3*D_MODEL)          // 3072

// ---------------- scratch (static device globals; no allocation) ----------
__device__ float g_q[BATCH*NHEAD*HDIM*SEQ];     // [B,H,Dh,T]
__device__ float g_k[BATCH*NHEAD*HDIM*SEQ];     // [B,H,Dh,T]
__device__ float g_v[BATCH*NHEAD*SEQ*HDIM];     // [B,H,T,Dh]
__device__ float g_attn[MTOT*D_MODEL];          // [B,T,C]

// ---------------- tf32 mma helpers ----------------------------------------
__device__ __forceinline__ uint32_t f2tf(float x) {
    uint32_t r; asm("cvt.rna.tf32.f32 %0, %1;" : "=r"(r) : "f"(x)); return r;
}
__device__ __forceinline__ uint4 cvt4(float4 v) {
    return make_uint4(f2tf(v.x), f2tf(v.y), f2tf(v.z), f2tf(v.w));
}
__device__ __forceinline__ uint4 cvt4s(float4 v, float s) {
    return make_uint4(f2tf(v.x*s), f2tf(v.y*s), f2tf(v.z*s), f2tf(v.w*s));
}
__device__ __forceinline__ void mma8(float* c,
    uint32_t a0, uint32_t a1, uint32_t a2, uint32_t a3,
    uint32_t b0, uint32_t b1)
{
    asm volatile(
        "mma.sync.aligned.m16n8k8.row.col.f32.tf32.tf32.f32 "
        "{%0,%1,%2,%3}, {%4,%5,%6,%7}, {%8,%9}, {%0,%1,%2,%3};"
        : "+f"(c[0]), "+f"(c[1]), "+f"(c[2]), "+f"(c[3])
        : "r"(a0), "r"(a1), "r"(a2), "r"(a3), "r"(b0), "r"(b1));
}

// ===========================================================================
// tf32 MMA GEMM: CTA tile 128x128, 128 threads (4 warps), warp tile 64x64.
// K chunk 16, double-buffered, one sync per chunk.
// sA [128][20] (row, k) ; sB [16][136] (k, n).
// ===========================================================================
#define SA_STRIDE 20
#define SB_STRIDE 136

__device__ __forceinline__ void gemm_tile_64(
    const float* __restrict__ A, const float* __restrict__ W, int ldW,
    int m0, int n0,
    uint32_t (*sA)[128*SA_STRIDE], uint32_t (*sB)[16*SB_STRIDE],
    float acc[4][8][4])
{
    const int tid  = threadIdx.x;
    const int lane = tid & 31;
    const int wid  = tid >> 5;
    const int wm   = wid & 1;      // 0/1 -> rows 0/64
    const int wn   = wid >> 1;     // 0/1 -> cols 0/64
    const int lq   = lane & 3;
    const int gq   = lane >> 2;

    // loader: A row per thread (16 floats); B row tid>>3, cols (tid&7)*4 + i*32
    const float* Abase = A + (size_t)(m0 + tid)*D_MODEL;
    const int brow = tid >> 3;
    const int bcol = (tid & 7)*4;
    const float* Wbase = W + (size_t)brow*ldW + n0 + bcol;

    float4 pa[4], pb[4];
    #pragma unroll
    for (int i = 0; i < 4; i++) {
        pa[i] = *(const float4*)(Abase + i*4);
        pb[i] = *(const float4*)(Wbase + i*32);
    }
    #pragma unroll
    for (int i = 0; i < 4; i++) {
        *(uint4*)&sA[0][tid*SA_STRIDE + i*4]          = cvt4(pa[i]);
        *(uint4*)&sB[0][brow*SB_STRIDE + bcol + i*32] = cvt4(pb[i]);
    }
    __syncthreads();

    for (int c = 0; c < 64; c++) {
        const int buf = c & 1;
        if (c < 63) {
            int k0 = (c + 1) * 16;
            #pragma unroll
            for (int i = 0; i < 4; i++) {
                pa[i] = *(const float4*)(Abase + k0 + i*4);
                pb[i] = *(const float4*)(Wbase + (size_t)k0*ldW + i*32);
            }
        }

        #pragma unroll
        for (int kk = 0; kk < 2; kk++) {
            const int kb = kk*8 + lq;
            uint32_t a[4][4];
            #pragma unroll
            for (int mt = 0; mt < 4; mt++) {
                int r = wm*64 + mt*16 + gq;
                a[mt][0] = sA[buf][ r      *SA_STRIDE + kb    ];
                a[mt][1] = sA[buf][(r + 8) *SA_STRIDE + kb    ];
                a[mt][2] = sA[buf][ r      *SA_STRIDE + kb + 4];
                a[mt][3] = sA[buf][(r + 8) *SA_STRIDE + kb + 4];
            }
            #pragma unroll
            for (int nt = 0; nt < 8; nt++) {
                int nb = wn*64 + nt*8 + gq;
                uint32_t b0 = sB[buf][ kb      *SB_STRIDE + nb];
                uint32_t b1 = sB[buf][(kb + 4) *SB_STRIDE + nb];
                #pragma unroll
                for (int mt = 0; mt < 4; mt++)
                    mma8(acc[mt][nt], a[mt][0], a[mt][1], a[mt][2], a[mt][3], b0, b1);
            }
        }

        if (c < 63) {
            int nb = buf ^ 1;
            #pragma unroll
            for (int i = 0; i < 4; i++) {
                *(uint4*)&sA[nb][tid*SA_STRIDE + i*4]          = cvt4(pa[i]);
                *(uint4*)&sB[nb][brow*SB_STRIDE + bcol + i*32] = cvt4(pb[i]);
            }
        }
        __syncthreads();
    }
}

// ---- GEMM 1: qkv = x @ w_qkv + b, scatter q/k transposed, v direct --------
__global__ __launch_bounds__(128,2) void qkv_mma_kernel(
    const float* __restrict__ x,
    const float* __restrict__ w,
    const float* __restrict__ bias)
{
    __shared__ uint32_t sA[2][128*SA_STRIDE];
    __shared__ uint32_t sB[2][16*SB_STRIDE];

    const int n0 = blockIdx.x * 128;
    const int m0 = blockIdx.y * 128;
    const int lane = threadIdx.x & 31;
    const int wid  = threadIdx.x >> 5;
    const int wm = wid & 1, wn = wid >> 1;
    const int lq = lane & 3, gq = lane >> 2;

    float acc[4][8][4];
    #pragma unroll
    for (int i = 0; i < 4; i++)
        #pragma unroll
        for (int j = 0; j < 8; j++)
            #pragma unroll
            for (int k = 0; k < 4; k++) acc[i][j][k] = 0.f;

    gemm_tile_64(x, w, NQKV, m0, n0, sA, sB, acc);

    #pragma unroll
    for (int mt = 0; mt < 4; mt++) {
        int rbase = m0 + wm*64 + mt*16 + gq;
        #pragma unroll
        for (int half = 0; half < 2; half++) {
            int row = rbase + half*8;
            int bb = row >> 11;
            int t  = row & 2047;
            #pragma unroll
            for (int nt = 0; nt < 8; nt++) {
                int n = n0 + wn*64 + nt*8 + lq*2;
                float v0 = acc[mt][nt][half*2+0] + __ldg(bias + n);
                float v1 = acc[mt][nt][half*2+1] + __ldg(bias + n + 1);
                int sec = n >> 10;
                int h   = (n >> 6) & 15;
                int d   = n & 63;
                int bh  = bb*NHEAD + h;
                if (sec == 2) {
                    *(float2*)&g_v[((size_t)bh*SEQ + t)*HDIM + d] = make_float2(v0, v1);
                } else {
                    float* p = sec ? g_k : g_q;
                    p[((size_t)bh*HDIM + d    )*SEQ + t] = v0;
                    p[((size_t)bh*HDIM + d + 1)*SEQ + t] = v1;
                }
            }
        }
    }
}

// ---- GEMM 3: out = attn @ w_out + b ----------------------------------------
__global__ __launch_bounds__(128,2) void out_mma_kernel(
    const float* __restrict__ w,
    const float* __restrict__ bias,
    float* __restrict__ out)
{
    __shared__ uint32_t sA[2][128*SA_STRIDE];
    __shared__ uint32_t sB[2][16*SB_STRIDE];

    const int n0 = blockIdx.x * 128;
    const int m0 = blockIdx.y * 128;
    const int lane = threadIdx.x & 31;
    const int wid  = threadIdx.x >> 5;
    const int wm = wid & 1, wn = wid >> 1;
    const int lq = lane & 3, gq = lane >> 2;

    float acc[4][8][4];
    #pragma unroll
    for (int i = 0; i < 4; i++)
        #pragma unroll
        for (int j = 0; j < 8; j++)
            #pragma unroll
            for (int k = 0; k < 4; k++) acc[i][j][k] = 0.f;

    gemm_tile_64(g_attn, w, D_MODEL, m0, n0, sA, sB, acc);

    #pragma unroll
    for (int mt = 0; mt < 4; mt++) {
        int rbase = m0 + wm*64 + mt*16 + gq;
        #pragma unroll
        for (int half = 0; half < 2; half++) {
            int row = rbase + half*8;
            #pragma unroll
            for (int nt = 0; nt < 8; nt++) {
                int n = n0 + wn*64 + nt*8 + lq*2;
                float v0 = acc[mt][nt][half*2+0] + __ldg(bias + n);
                float v1 = acc[mt][nt][half*2+1] + __ldg(bias + n + 1);
                *(float2*)&out[(size_t)row*D_MODEL + n] = make_float2(v0, v1);
            }
        }
    }
}

// ===========================================================================
// Flash attention with tf32 MMA. QTILE=128 rows/CTA, KTILE=64, 8 warps.
// Q fragments hoisted into registers (loop-invariant). Base-2 softmax.
// smem (uint32 words):
//   Qs [64][132]  off 0      (d, t)   8448
//   Kt [64][68]   off 8448   (d, c)   4352
//   Vs [64][68]   off 12800  (c, d)   4352
//   Ps [128][68]  off 17152  (r, c)   8704
#define QTILE 128
#define KTILE 64
#define FL_OFF_KT 8448
#define FL_OFF_VS 12800
#define FL_OFF_PS 17152
#define FLASH_SMEM_WORDS 25856
#define FLASH_SMEM_BYTES (FLASH_SMEM_WORDS*4)

__global__ __launch_bounds__(256,2) void flash_mma_kernel()
{
    extern __shared__ uint32_t smu[];
    uint32_t* Qs = smu;                 // [d][t] stride 132
    uint32_t* Kt = smu + FL_OFF_KT;     // [d][c] stride 68
    uint32_t* Vs = smu + FL_OFF_VS;     // [c][d] stride 68
    uint32_t* Ps = smu + FL_OFF_PS;     // [r][c] stride 68

    const int tid  = threadIdx.x;
    const int lane = tid & 31;
    const int wid  = tid >> 5;
    const int lq   = lane & 3;
    const int gq   = lane >> 2;
    const int r0   = wid * 16;

    const int qt = blockIdx.x;
    const int h  = blockIdx.y;
    const int bb = blockIdx.z;
    const int bh = bb*NHEAD + h;

    const float* qT = g_q + (size_t)bh*HDIM*SEQ + qt*QTILE;  // + d*SEQ + t
    const float* kT = g_k + (size_t)bh*HDIM*SEQ;             // + d*SEQ + c
    const float* vb = g_v + (size_t)bh*SEQ*HDIM;             // + c*HDIM + d

    // scale folded with log2(e): softmax computed in base 2
    const float scale = 0.125f * 1.4426950408889634f;

    // load Q tile [d][t] as tf32, pre-scaled
    for (int i = tid; i < 64*32; i += 256) {
        int d = i >> 5, t4 = i & 31;
        float4 v = *(const float4*)(qT + (size_t)d*SEQ + t4*4);
        *(uint4*)&Qs[d*132 + t4*4] = cvt4s(v, scale);
    }
    __syncthreads();

    const int row0 = r0 + gq;
    const int row1 = row0 + 8;

    // hoist Q fragments (invariant across all K tiles)
    uint32_t qa[8][4];
    #pragma unroll
    for (int kk = 0; kk < 8; kk++) {
        int kb = kk*8 + lq;
        qa[kk][0] = Qs[ kb     *132 + row0];
        qa[kk][1] = Qs[ kb     *132 + row1];
        qa[kk][2] = Qs[(kb + 4)*132 + row0];
        qa[kk][3] = Qs[(kb + 4)*132 + row1];
    }

    float m0 = -1e30f, m1 = -1e30f, l0 = 0.f, l1 = 0.f;
    float o[8][4];
    #pragma unroll
    for (int i = 0; i < 8; i++)
        #pragma unroll
        for (int j = 0; j < 4; j++) o[i][j] = 0.f;

    for (int kt = 0; kt < SEQ/KTILE; kt++) {
        __syncthreads();   // prev iter done reading Kt/Vs (Qs no longer read)

        for (int i = tid; i < 64*16; i += 256) {
            int d = i >> 4, c4 = i & 15;
            float4 v = *(const float4*)(kT + (size_t)d*SEQ + kt*KTILE + c4*4);
            *(uint4*)&Kt[d*68 + c4*4] = cvt4(v);
        }
        for (int i = tid; i < 64*16; i += 256) {
            int c = i >> 4, d4 = i & 15;
            float4 v = *(const float4*)(vb + (size_t)(kt*KTILE + c)*HDIM + d4*4);
            *(uint4*)&Vs[c*68 + d4*4] = cvt4(v);
        }
        __syncthreads();

        // ---- S = Q K^T (base-2 scaled) : warp tile 16 x 64 ----
        float s[8][4];
        #pragma unroll
        for (int nt = 0; nt < 8; nt++)
            #pragma unroll
            for (int j = 0; j < 4; j++) s[nt][j] = 0.f;

        #pragma unroll
        for (int kk = 0; kk < 8; kk++) {
            int kb = kk*8 + lq;
            #pragma unroll
            for (int nt = 0; nt < 8; nt++) {
                uint32_t b0 = Kt[ kb     *68 + nt*8 + gq];
                uint32_t b1 = Kt[(kb + 4)*68 + nt*8 + gq];
                mma8(s[nt], qa[kk][0], qa[kk][1], qa[kk][2], qa[kk][3], b0, b1);
            }
        }

        // ---- online softmax (base 2) ----
        float mt0 = -1e30f, mt1 = -1e30f;
        #pragma unroll
        for (int nt = 0; nt < 8; nt++) {
            mt0 = fmaxf(mt0, fmaxf(s[nt][0], s[nt][1]));
            mt1 = fmaxf(mt1, fmaxf(s[nt][2], s[nt][3]));
        }
        mt0 = fmaxf(mt0, __shfl_xor_sync(0xffffffffu, mt0, 1));
        mt0 = fmaxf(mt0, __shfl_xor_sync(0xffffffffu, mt0, 2));
        mt1 = fmaxf(mt1, __shfl_xor_sync(0xffffffffu, mt1, 1));
        mt1 = fmaxf(mt1, __shfl_xor_sync(0xffffffffu, mt1, 2));

        float mn0 = fmaxf(m0, mt0);
        float mn1 = fmaxf(m1, mt1);
        float corr0 = exp2f(m0 - mn0);
        float corr1 = exp2f(m1 - mn1);
        m0 = mn0; m1 = mn1;

        float sum0 = 0.f, sum1 = 0.f;
        #pragma unroll
        for (int nt = 0; nt < 8; nt++) {
            float p0 = exp2f(s[nt][0] - mn0);
            float p1 = exp2f(s[nt][1] - mn0);
            float p2 = exp2f(s[nt][2] - mn1);
            float p3 = exp2f(s[nt][3] - mn1);
            sum0 += p0 + p1;
            sum1 += p2 + p3;
            *(uint2*)&Ps[row0*68 + nt*8 + lq*2] = make_uint2(f2tf(p0), f2tf(p1));
            *(uint2*)&Ps[row1*68 + nt*8 + lq*2] = make_uint2(f2tf(p2), f2tf(p3));
        }
        sum0 += __shfl_xor_sync(0xffffffffu, sum0, 1);
        sum0 += __shfl_xor_sync(0xffffffffu, sum0, 2);
        sum1 += __shfl_xor_sync(0xffffffffu, sum1, 1);
        sum1 += __shfl_xor_sync(0xffffffffu, sum1, 2);
        l0 = l0*corr0 + sum0;
        l1 = l1*corr1 + sum1;

        #pragma unroll
        for (int nt = 0; nt < 8; nt++) {
            o[nt][0] *= corr0; o[nt][1] *= corr0;
            o[nt][2] *= corr1; o[nt][3] *= corr1;
        }
        __syncwarp();

        // ---- O += P V : warp tile 16 x 64 ----
        #pragma unroll
        for (int kk = 0; kk < 8; kk++) {
            int kb = kk*8 + lq;
            uint32_t a0 = Ps[row0*68 + kb    ];
            uint32_t a1 = Ps[row1*68 + kb    ];
            uint32_t a2 = Ps[row0*68 + kb + 4];
            uint32_t a3 = Ps[row1*68 + kb + 4];
            #pragma unroll
            for (int nt = 0; nt < 8; nt++) {
                uint32_t b0 = Vs[ kb     *68 + nt*8 + gq];
                uint32_t b1 = Vs[(kb + 4)*68 + nt*8 + gq];
                mma8(o[nt], a0, a1, a2, a3, b0, b1);
            }
        }
        __syncwarp();
    }

    float inv0 = 1.0f / l0;
    float inv1 = 1.0f / l1;
    #pragma unroll
    for (int nt = 0; nt < 8; nt++) {
        int d = nt*8 + lq*2;
        float* dst0 = g_attn + (size_t)(bb*SEQ + qt*QTILE + row0)*D_MODEL + h*64 + d;
        float* dst1 = g_attn + (size_t)(bb*SEQ + qt*QTILE + row1)*D_MODEL + h*64 + d;
        *(float2*)dst0 = make_float2(o[nt][0]*inv0, o[nt][1]*inv0);
        *(float2*)dst1 = make_float2(o[nt][2]*inv1, o[nt][3]*inv1);
    }
}

// ===========================================================================
extern "C" void kernel_launch(void* const* d_in, const int* in_sizes, int n_in,
                              void* d_out, int out_size)
{
    const float* x     = (const float*)d_in[0];
    const float* w_qkv = (const float*)d_in[1];
    const float* b_qkv = (const float*)d_in[2];
    const float* w_out = (const float*)d_in[3];
    const float* b_out = (const float*)d_in[4];
    float* out = (float*)d_out;

    (void)in_sizes; (void)n_in; (void)out_size;

    cudaFuncSetAttribute(flash_mma_kernel,
                         cudaFuncAttributeMaxDynamicSharedMemorySize,
                         FLASH_SMEM_BYTES);

    // 1) QKV GEMM (tf32 MMA) + bias + scatter
    {
        dim3 grid(NQKV/128, MTOT/128);    // (24, 32)
        qkv_mma_kernel<<<grid, 128>>>(x, w_qkv, b_qkv);
    }
    // 2) flash attention (tf32 MMA)
    {
        dim3 grid(SEQ/QTILE, NHEAD, BATCH); // (16, 16, 2)
        flash_mma_kernel<<<grid, 256, FLASH_SMEM_BYTES>>>();
    }
    // 3) out GEMM (tf32 MMA) + bias
    {
        dim3 grid(D_MODEL/128, MTOT/128); // (8, 32)
        out_mma_kernel<<<grid, 128>>>(w_out, b_out, out);
    }
}

// round 7
// speedup vs baseline: 3.9480x; 1.5996x over previous
#include <cuda_runtime.h>
#include <cstdint>

#define D_MODEL 1024
#define NHEAD   16
#define HDIM    64
#define BATCH   2
#define SEQ     2048
#define MTOT    (BATCH*SEQ)          // 4096
#define NQKV    (3*D_MODEL)          // 3072

// ---------------- scratch (static device globals; no allocation) ----------
__device__ float g_q[BATCH*NHEAD*HDIM*SEQ];     // [B,H,Dh,T]
__device__ float g_k[BATCH*NHEAD*HDIM*SEQ];     // [B,H,Dh,T]
__device__ float g_v[BATCH*NHEAD*SEQ*HDIM];     // [B,H,T,Dh]
__device__ float g_attn[MTOT*D_MODEL];          // [B,T,C]

// ---------------- helpers ---------------------------------------------------
__device__ __forceinline__ uint32_t smem_u32(const void* p) {
    uint32_t a;
    asm("{ .reg .u64 t; cvta.to.shared.u64 t, %1; cvt.u32.u64 %0, t; }" : "=r"(a) : "l"(p));
    return a;
}
__device__ __forceinline__ uint32_t f2tf(float x) {
    uint32_t r; asm("cvt.rna.tf32.f32 %0, %1;" : "=r"(r) : "f"(x)); return r;
}
__device__ __forceinline__ uint4 cvt4s(float4 v, float s) {
    return make_uint4(f2tf(v.x*s), f2tf(v.y*s), f2tf(v.z*s), f2tf(v.w*s));
}
__device__ __forceinline__ void mma8(float* c,
    uint32_t a0, uint32_t a1, uint32_t a2, uint32_t a3,
    uint32_t b0, uint32_t b1)
{
    asm volatile(
        "mma.sync.aligned.m16n8k8.row.col.f32.tf32.tf32.f32 "
        "{%0,%1,%2,%3}, {%4,%5,%6,%7}, {%8,%9}, {%0,%1,%2,%3};"
        : "+f"(c[0]), "+f"(c[1]), "+f"(c[2]), "+f"(c[3])
        : "r"(a0), "r"(a1), "r"(a2), "r"(a3), "r"(b0), "r"(b1));
}
__device__ __forceinline__ void cp16(uint32_t dst, const void* src) {
    asm volatile("cp.async.cg.shared.global [%0], [%1], 16;" :: "r"(dst), "l"(src));
}
#define CP_COMMIT() asm volatile("cp.async.commit_group;" ::: "memory")
#define CP_WAIT(n)  asm volatile("cp.async.wait_group %0;" :: "n"(n) : "memory")

// ===========================================================================
// tf32 MMA GEMM, 4-stage cp.async pipeline. CTA tile 128x128, 128 threads
// (4 warps, warp tile 64x64). K chunk 16. No cvt: raw fp32 bits read as tf32.
// sA stage: [128][20]  (2560 words);  sB stage: [16][136] (2176 words).
// ===========================================================================
#define SA_ST 2560
#define SB_ST 2176
#define SB_BASE (4*SA_ST)            // 10240
#define GEMM_SMEM_WORDS (4*SA_ST + 4*SB_ST)    // 18944
#define GEMM_SMEM_BYTES (GEMM_SMEM_WORDS*4)    // 75776

__device__ __forceinline__ void gemm_issue_stage(
    uint32_t smem_u, int st,
    const float* __restrict__ A, const float* __restrict__ W, int ldW,
    int m0, int n0, int k0, int tid)
{
    uint32_t sa = smem_u + (st*SA_ST)*4;
    uint32_t sb = smem_u + (SB_BASE + st*SB_ST)*4;
    const int ar = tid >> 2, ac = (tid & 3)*4;
    #pragma unroll
    for (int i = 0; i < 4; i++) {
        int row = i*32 + ar;
        cp16(sa + (row*20 + ac)*4, A + (size_t)(m0+row)*D_MODEL + k0 + ac);
    }
    const int br = tid >> 5, bc = (tid & 31)*4;
    #pragma unroll
    for (int i = 0; i < 4; i++) {
        int r = i*4 + br;
        cp16(sb + (r*136 + bc)*4, W + (size_t)(k0+r)*ldW + n0 + bc);
    }
}

__device__ __forceinline__ void gemm_tile_cp(
    uint32_t* sm, uint32_t smem_u,
    const float* __restrict__ A, const float* __restrict__ W, int ldW,
    int m0, int n0, float acc[4][8][4])
{
    const int tid  = threadIdx.x;
    const int lane = tid & 31;
    const int wid  = tid >> 5;
    const int wm   = wid & 1;
    const int wn   = wid >> 1;
    const int lq   = lane & 3;
    const int gq   = lane >> 2;

    gemm_issue_stage(smem_u, 0, A, W, ldW, m0, n0, 0,  tid); CP_COMMIT();
    gemm_issue_stage(smem_u, 1, A, W, ldW, m0, n0, 16, tid); CP_COMMIT();
    gemm_issue_stage(smem_u, 2, A, W, ldW, m0, n0, 32, tid); CP_COMMIT();

    for (int s = 0; s < 64; s++) {
        CP_WAIT(2);
        __syncthreads();
        if (s + 3 < 64) {
            gemm_issue_stage(smem_u, (s+3)&3, A, W, ldW, m0, n0, (s+3)*16, tid);
            CP_COMMIT();
        }
        const uint32_t* bufA = sm + (s&3)*SA_ST;
        const uint32_t* bufB = sm + SB_BASE + (s&3)*SB_ST;

        #pragma unroll
        for (int kk = 0; kk < 2; kk++) {
            const int kb = kk*8 + lq;
            uint32_t a[4][4];
            #pragma unroll
            for (int mt = 0; mt < 4; mt++) {
                int r = wm*64 + mt*16 + gq;
                a[mt][0] = bufA[ r      *20 + kb    ];
                a[mt][1] = bufA[(r + 8) *20 + kb    ];
                a[mt][2] = bufA[ r      *20 + kb + 4];
                a[mt][3] = bufA[(r + 8) *20 + kb + 4];
            }
            #pragma unroll
            for (int nt = 0; nt < 8; nt++) {
                int nb = wn*64 + nt*8 + gq;
                uint32_t b0 = bufB[ kb      *136 + nb];
                uint32_t b1 = bufB[(kb + 4) *136 + nb];
                #pragma unroll
                for (int mt = 0; mt < 4; mt++)
                    mma8(acc[mt][nt], a[mt][0], a[mt][1], a[mt][2], a[mt][3], b0, b1);
            }
        }
    }
}

// ---- GEMM 1: qkv = x @ w_qkv + b, scatter q/k transposed, v direct --------
__global__ __launch_bounds__(128,2) void qkv_mma_kernel(
    const float* __restrict__ x,
    const float* __restrict__ w,
    const float* __restrict__ bias)
{
    extern __shared__ uint32_t smg[];
    uint32_t smem_u = smem_u32(smg);

    const int n0 = blockIdx.x * 128;
    const int m0 = blockIdx.y * 128;
    const int lane = threadIdx.x & 31;
    const int wid  = threadIdx.x >> 5;
    const int wm = wid & 1, wn = wid >> 1;
    const int lq = lane & 3, gq = lane >> 2;

    float acc[4][8][4];
    #pragma unroll
    for (int i = 0; i < 4; i++)
        #pragma unroll
        for (int j = 0; j < 8; j++)
            #pragma unroll
            for (int k = 0; k < 4; k++) acc[i][j][k] = 0.f;

    gemm_tile_cp(smg, smem_u, x, w, NQKV, m0, n0, acc);

    #pragma unroll
    for (int mt = 0; mt < 4; mt++) {
        int rbase = m0 + wm*64 + mt*16 + gq;
        #pragma unroll
        for (int half = 0; half < 2; half++) {
            int row = rbase + half*8;
            int bb = row >> 11;
            int t  = row & 2047;
            #pragma unroll
            for (int nt = 0; nt < 8; nt++) {
                int n = n0 + wn*64 + nt*8 + lq*2;
                float v0 = acc[mt][nt][half*2+0] + __ldg(bias + n);
                float v1 = acc[mt][nt][half*2+1] + __ldg(bias + n + 1);
                int sec = n >> 10;
                int h   = (n >> 6) & 15;
                int d   = n & 63;
                int bh  = bb*NHEAD + h;
                if (sec == 2) {
                    *(float2*)&g_v[((size_t)bh*SEQ + t)*HDIM + d] = make_float2(v0, v1);
                } else {
                    float* p = sec ? g_k : g_q;
                    p[((size_t)bh*HDIM + d    )*SEQ + t] = v0;
                    p[((size_t)bh*HDIM + d + 1)*SEQ + t] = v1;
                }
            }
        }
    }
}

// ---- GEMM 3: out = attn @ w_out + b ----------------------------------------
__global__ __launch_bounds__(128,2) void out_mma_kernel(
    const float* __restrict__ w,
    const float* __restrict__ bias,
    float* __restrict__ out)
{
    extern __shared__ uint32_t smg[];
    uint32_t smem_u = smem_u32(smg);

    const int n0 = blockIdx.x * 128;
    const int m0 = blockIdx.y * 128;
    const int lane = threadIdx.x & 31;
    const int wid  = threadIdx.x >> 5;
    const int wm = wid & 1, wn = wid >> 1;
    const int lq = lane & 3, gq = lane >> 2;

    float acc[4][8][4];
    #pragma unroll
    for (int i = 0; i < 4; i++)
        #pragma unroll
        for (int j = 0; j < 8; j++)
            #pragma unroll
            for (int k = 0; k < 4; k++) acc[i][j][k] = 0.f;

    gemm_tile_cp(smg, smem_u, g_attn, w, D_MODEL, m0, n0, acc);

    #pragma unroll
    for (int mt = 0; mt < 4; mt++) {
        int rbase = m0 + wm*64 + mt*16 + gq;
        #pragma unroll
        for (int half = 0; half < 2; half++) {
            int row = rbase + half*8;
            #pragma unroll
            for (int nt = 0; nt < 8; nt++) {
                int n = n0 + wn*64 + nt*8 + lq*2;
                float v0 = acc[mt][nt][half*2+0] + __ldg(bias + n);
                float v1 = acc[mt][nt][half*2+1] + __ldg(bias + n + 1);
                *(float2*)&out[(size_t)row*D_MODEL + n] = make_float2(v0, v1);
            }
        }
    }
}

// ===========================================================================
// Flash attention, tf32 MMA, cp.async 3-buffer K/V pipeline, P via shuffles.
// QTILE=128 rows/CTA, KTILE=64, 8 warps (warp owns 16 rows).
// smem: 3 KV buffers of (K [64][72] + V [64][72]) = 9216 words each.
//   buf b at b*9216; K at +0, V at +4608.
// Qs [64][132] (8448 words) overlays buffer 2 (first written at iter 0).
#define QTILE 128
#define KTILE 64
#define KVSTR 72
#define KBUF 4608
#define BUF_WORDS 9216
#define FLASH_SMEM_WORDS (3*BUF_WORDS)          // 27648
#define FLASH_SMEM_BYTES (FLASH_SMEM_WORDS*4)   // 110592
#define QS_OFF (2*BUF_WORDS)                    // Qs overlays buffer 2

__device__ __forceinline__ void flash_issue_kv(
    uint32_t smem_u, int bufidx, int kt,
    const float* __restrict__ kT, const float* __restrict__ vb, int tid)
{
    uint32_t kb = smem_u + (bufidx*BUF_WORDS)*4;
    uint32_t vbuf = kb + KBUF*4;
    const int rhi = tid >> 4;          // 0..15
    const int c16 = (tid & 15)*4;      // 0..60
    #pragma unroll
    for (int i = 0; i < 4; i++) {
        int d = i*16 + rhi;
        cp16(kb + (d*KVSTR + c16)*4, kT + (size_t)d*SEQ + kt*KTILE + c16);
    }
    #pragma unroll
    for (int i = 0; i < 4; i++) {
        int c = i*16 + rhi;
        cp16(vbuf + (c*KVSTR + c16)*4, vb + (size_t)(kt*KTILE + c)*HDIM + c16);
    }
}

__global__ __launch_bounds__(256,2) void flash_mma_kernel()
{
    extern __shared__ uint32_t smu[];
    uint32_t smem_u = smem_u32(smu);
    uint32_t* Qs = smu + QS_OFF;        // [d][t] stride 132, prologue only

    const int tid  = threadIdx.x;
    const int lane = tid & 31;
    const int wid  = tid >> 5;
    const int lq   = lane & 3;
    const int gq   = lane >> 2;
    const int r0   = wid * 16;
    const int psrc = (lane & 28) | (lq >> 1);
    const int odd  = lq & 1;

    const int qt = blockIdx.x;
    const int h  = blockIdx.y;
    const int bb = blockIdx.z;
    const int bh = bb*NHEAD + h;

    const float* qT = g_q + (size_t)bh*HDIM*SEQ + qt*QTILE;
    const float* kT = g_k + (size_t)bh*HDIM*SEQ;
    const float* vb = g_v + (size_t)bh*SEQ*HDIM;

    // start K/V pipeline for tiles 0,1 (buffers 0,1)
    flash_issue_kv(smem_u, 0, 0, kT, vb, tid); CP_COMMIT();
    flash_issue_kv(smem_u, 1, 1, kT, vb, tid); CP_COMMIT();

    // scale with log2(e) folded: softmax in base 2
    const float scale = 0.125f * 1.4426950408889634f;

    // load Q tile [d][t] as tf32 (rna), pre-scaled, into Qs (buffer-2 region)
    for (int i = tid; i < 64*32; i += 256) {
        int d = i >> 5, t4 = i & 31;
        float4 v = *(const float4*)(qT + (size_t)d*SEQ + t4*4);
        *(uint4*)&Qs[d*132 + t4*4] = cvt4s(v, scale);
    }
    __syncthreads();

    const int row0 = r0 + gq;
    const int row1 = row0 + 8;

    uint32_t qa[8][4];
    #pragma unroll
    for (int kk = 0; kk < 8; kk++) {
        int kb = kk*8 + lq;
        qa[kk][0] = Qs[ kb     *132 + row0];
        qa[kk][1] = Qs[ kb     *132 + row1];
        qa[kk][2] = Qs[(kb + 4)*132 + row0];
        qa[kk][3] = Qs[(kb + 4)*132 + row1];
    }

    float m0 = -1e30f, m1 = -1e30f, l0 = 0.f, l1 = 0.f;
    float o[8][4];
    #pragma unroll
    for (int i = 0; i < 8; i++)
        #pragma unroll
        for (int j = 0; j < 4; j++) o[i][j] = 0.f;

    for (int kt = 0; kt < SEQ/KTILE; kt++) {
        CP_WAIT(1);
        __syncthreads();
        if (kt + 2 < SEQ/KTILE) {
            flash_issue_kv(smem_u, (kt+2)%3, kt+2, kT, vb, tid);
            CP_COMMIT();
        }
        const uint32_t* Kb = smu + (kt%3)*BUF_WORDS;
        const uint32_t* Vb = Kb + KBUF;

        // ---- S = Q K^T (base-2 scaled) ----
        float s[8][4];
        #pragma unroll
        for (int nt = 0; nt < 8; nt++)
            #pragma unroll
            for (int j = 0; j < 4; j++) s[nt][j] = 0.f;

        #pragma unroll
        for (int kk = 0; kk < 8; kk++) {
            int kb = kk*8 + lq;
            #pragma unroll
            for (int nt = 0; nt < 8; nt++) {
                uint32_t b0 = Kb[ kb     *KVSTR + nt*8 + gq];
                uint32_t b1 = Kb[(kb + 4)*KVSTR + nt*8 + gq];
                mma8(s[nt], qa[kk][0], qa[kk][1], qa[kk][2], qa[kk][3], b0, b1);
            }
        }

        // ---- online softmax (base 2) ----
        float mt0 = -1e30f, mt1 = -1e30f;
        #pragma unroll
        for (int nt = 0; nt < 8; nt++) {
            mt0 = fmaxf(mt0, fmaxf(s[nt][0], s[nt][1]));
            mt1 = fmaxf(mt1, fmaxf(s[nt][2], s[nt][3]));
        }
        mt0 = fmaxf(mt0, __shfl_xor_sync(0xffffffffu, mt0, 1));
        mt0 = fmaxf(mt0, __shfl_xor_sync(0xffffffffu, mt0, 2));
        mt1 = fmaxf(mt1, __shfl_xor_sync(0xffffffffu, mt1, 1));
        mt1 = fmaxf(mt1, __shfl_xor_sync(0xffffffffu, mt1, 2));

        float mn0 = fmaxf(m0, mt0);
        float mn1 = fmaxf(m1, mt1);
        float corr0 = exp2f(m0 - mn0);
        float corr1 = exp2f(m1 - mn1);
        m0 = mn0; m1 = mn1;

        uint32_t pu[8][4];
        float sum0 = 0.f, sum1 = 0.f;
        #pragma unroll
        for (int nt = 0; nt < 8; nt++) {
            float p0 = exp2f(s[nt][0] - mn0);
            float p1 = exp2f(s[nt][1] - mn0);
            float p2 = exp2f(s[nt][2] - mn1);
            float p3 = exp2f(s[nt][3] - mn1);
            sum0 += p0 + p1;
            sum1 += p2 + p3;
            pu[nt][0] = f2tf(p0); pu[nt][1] = f2tf(p1);
            pu[nt][2] = f2tf(p2); pu[nt][3] = f2tf(p3);
        }
        sum0 += __shfl_xor_sync(0xffffffffu, sum0, 1);
        sum0 += __shfl_xor_sync(0xffffffffu, sum0, 2);
        sum1 += __shfl_xor_sync(0xffffffffu, sum1, 1);
        sum1 += __shfl_xor_sync(0xffffffffu, sum1, 2);
        l0 = l0*corr0 + sum0;
        l1 = l1*corr1 + sum1;

        #pragma unroll
        for (int nt = 0; nt < 8; nt++) {
            o[nt][0] *= corr0; o[nt][1] *= corr0;
            o[nt][2] *= corr1; o[nt][3] *= corr1;
        }

        // ---- O += P V ; P fragments gathered from S accum via shuffles ----
        #pragma unroll
        for (int kk = 0; kk < 8; kk++) {
            uint32_t v0 = __shfl_sync(0xffffffffu, pu[kk][0], psrc);
            uint32_t v1 = __shfl_sync(0xffffffffu, pu[kk][1], psrc);
            uint32_t w0 = __shfl_sync(0xffffffffu, pu[kk][2], psrc);
            uint32_t w1 = __shfl_sync(0xffffffffu, pu[kk][3], psrc);
            uint32_t u0 = __shfl_sync(0xffffffffu, pu[kk][0], psrc + 2);
            uint32_t u1 = __shfl_sync(0xffffffffu, pu[kk][1], psrc + 2);
            uint32_t x0 = __shfl_sync(0xffffffffu, pu[kk][2], psrc + 2);
            uint32_t x1 = __shfl_sync(0xffffffffu, pu[kk][3], psrc + 2);
            uint32_t a0 = odd ? v1 : v0;
            uint32_t a1 = odd ? w1 : w0;
            uint32_t a2 = odd ? u1 : u0;
            uint32_t a3 = odd ? x1 : x0;
            int kb = kk*8 + lq;
            #pragma unroll
            for (int nt = 0; nt < 8; nt++) {
                uint32_t b0 = Vb[ kb     *KVSTR + nt*8 + gq];
                uint32_t b1 = Vb[(kb + 4)*KVSTR + nt*8 + gq];
                mma8(o[nt], a0, a1, a2, a3, b0, b1);
            }
        }
    }

    float inv0 = 1.0f / l0;
    float inv1 = 1.0f / l1;
    #pragma unroll
    for (int nt = 0; nt < 8; nt++) {
        int d = nt*8 + lq*2;
        float* dst0 = g_attn + (size_t)(bb*SEQ + qt*QTILE + row0)*D_MODEL + h*64 + d;
        float* dst1 = g_attn + (size_t)(bb*SEQ + qt*QTILE + row1)*D_MODEL + h*64 + d;
        *(float2*)dst0 = make_float2(o[nt][0]*inv0, o[nt][1]*inv0);
        *(float2*)dst1 = make_float2(o[nt][2]*inv1, o[nt][3]*inv1);
    }
}

// ===========================================================================
extern "C" void kernel_launch(void* const* d_in, const int* in_sizes, int n_in,
                              void* d_out, int out_size)
{
    const float* x     = (const float*)d_in[0];
    const float* w_qkv = (const float*)d_in[1];
    const float* b_qkv = (const float*)d_in[2];
    const float* w_out = (const float*)d_in[3];
    const float* b_out = (const float*)d_in[4];
    float* out = (float*)d_out;

    (void)in_sizes; (void)n_in; (void)out_size;

    cudaFuncSetAttribute(qkv_mma_kernel,
                         cudaFuncAttributeMaxDynamicSharedMemorySize, GEMM_SMEM_BYTES);
    cudaFuncSetAttribute(out_mma_kernel,
                         cudaFuncAttributeMaxDynamicSharedMemorySize, GEMM_SMEM_BYTES);
    cudaFuncSetAttribute(flash_mma_kernel,
                         cudaFuncAttributeMaxDynamicSharedMemorySize, FLASH_SMEM_BYTES);

    // 1) QKV GEMM (tf32 MMA, cp.async) + bias + scatter
    {
        dim3 grid(NQKV/128, MTOT/128);    // (24, 32)
        qkv_mma_kernel<<<grid, 128, GEMM_SMEM_BYTES>>>(x, w_qkv, b_qkv);
    }
    // 2) flash attention (tf32 MMA, cp.async)
    {
        dim3 grid(SEQ/QTILE, NHEAD, BATCH); // (16, 16, 2)
        flash_mma_kernel<<<grid, 256, FLASH_SMEM_BYTES>>>();
    }
    // 3) out GEMM (tf32 MMA, cp.async) + bias
    {
        dim3 grid(D_MODEL/128, MTOT/128); // (8, 32)
        out_mma_kernel<<<grid, 128, GEMM_SMEM_BYTES>>>(w_out, b_out, out);
    }
}